// round 5
// baseline (speedup 1.0000x reference)
#include <cuda_runtime.h>
#include <cstdint>

#define Bn 64
#define Cn 64
#define On 64
#define Hn 32
#define Wn 32
#define Ln 1024
#define KKn 576
#define HP 34
#define WP 34

// padded, transposed x: [c][hp][wp][b], b innermost for coalesced unfold gathers
__device__ float g_xTp[Cn * HP * WP * Bn];

// ---------------------------------------------------------------------------
// Kernel 1: zero the padded border of g_xTp
// ---------------------------------------------------------------------------
__global__ void border_kernel() {
    int idx = blockIdx.x * 256 + threadIdx.x;       // 64 c * 132 border cells * 64 b
    if (idx >= Cn * 132 * Bn) return;
    int b = idx & 63;
    int r = idx >> 6;
    int c = r / 132;
    int cell = r % 132;
    int hp, wp;
    if (cell < 34)       { hp = 0;  wp = cell; }
    else if (cell < 68)  { hp = 33; wp = cell - 34; }
    else if (cell < 100) { hp = cell - 68 + 1;  wp = 0; }
    else                 { hp = cell - 100 + 1; wp = 33; }
    g_xTp[((c * HP + hp) * WP + wp) * Bn + b] = 0.0f;
}

// ---------------------------------------------------------------------------
// Kernel 2: transpose x (B,C,H,W) -> xTp[c][h+1][w+1][b] via smem tile
// ---------------------------------------------------------------------------
__global__ void transpose_kernel(const float* __restrict__ x) {
    __shared__ float t[32][65];
    int c = blockIdx.x & 63;
    int h = blockIdx.x >> 6;
    int tid = threadIdx.x;

    int w  = tid & 31;
    int b0 = tid >> 5;                     // 0..7
#pragma unroll
    for (int p = 0; p < 8; p++) {
        int b = b0 * 8 + p;
        t[w][b] = x[((b * Cn + c) * Hn + h) * Wn + w];  // 128B coalesced reads
    }
    __syncthreads();
    int b  = tid & 63;
    int wq = tid >> 6;                     // 0..3
#pragma unroll
    for (int p = 0; p < 8; p++) {
        int ww = wq * 8 + p;
        g_xTp[((c * HP + (h + 1)) * WP + (ww + 1)) * Bn + b] = t[ww][b];  // 256B coalesced writes
    }
}

// ---------------------------------------------------------------------------
// Kernel 3: main locally-connected GEMM
//   grid = 128 CTAs (8 pixels each), 512 threads
//   thread tid -> (b_t = tid&7, o_t = (tid>>3)&7, l = tid>>6)
//   per-thread 8o x 8b outer product at one pixel, fp32x2-packed over o
// ---------------------------------------------------------------------------
__device__ __forceinline__ void cpa16(float* dst, const float* src) {
    unsigned d = (unsigned)__cvta_generic_to_shared(dst);
    asm volatile("cp.async.cg.shared.global [%0], [%1], 16;" :: "r"(d), "l"(src));
}
__device__ __forceinline__ unsigned long long pk(float v) {
    unsigned long long r;
    asm("mov.b64 %0, {%1, %1};" : "=l"(r) : "f"(v));
    return r;
}
#define FFMA2(a, wv, uv) asm("fma.rn.f32x2 %0, %1, %2, %0;" : "+l"(a) : "l"(wv), "l"(uv))

__global__ __launch_bounds__(512, 1)
void lc_kernel(const float* __restrict__ weight, const float* __restrict__ bias,
               float* __restrict__ out) {
    extern __shared__ float smem[];
    float* w_s = smem;            // [2][8k][8l][64o]  (16KB per buf)
    float* u_s = smem + 8192;     // [2][8k][8l][64b]

    const int tid = threadIdx.x;
    const int bt  = tid & 7;
    const int ot  = (tid >> 3) & 7;
    const int lv  = tid >> 6;
    const int l0  = blockIdx.x << 3;
    const int h   = l0 >> 5;         // row (constant for the whole CTA)
    const int w0  = l0 & 31;

    // u cp.async mapping: thread covers 2 float4s (k2 and k2+4), fixed (l,b4)
    const int ub4  = tid & 15;
    const int ul   = (tid >> 4) & 7;
    const int uk2a = tid >> 7;       // 0..3

    // w LDG/STS mapping: thread covers (o, k2), 8 l-values (32B contiguous in gmem)
    const int wo  = tid & 63;
    const int wk2 = tid >> 6;        // 0..7

    unsigned long long acc[4][8];
#pragma unroll
    for (int i = 0; i < 4; i++)
#pragma unroll
        for (int j = 0; j < 8; j++) acc[i][j] = 0ULL;

    // ---- helpers as lambdas ----
    auto issue_u = [&](int ch, int buf) {
#pragma unroll
        for (int t = 0; t < 2; t++) {
            int k2 = uk2a + 4 * t;
            int k  = ch * 8 + k2;
            int c   = (k * 7282) >> 16;        // k/9, exact for k<576
            int rem = k - 9 * c;
            int i   = (rem * 11) >> 5;         // rem/3
            int j   = rem - 3 * i;
            const float* src = g_xTp + (((c * HP) + h + i) * WP + (w0 + ul + j)) * Bn + (ub4 << 2);
            cpa16(u_s + buf * 4096 + (k2 * 8 + ul) * 64 + (ub4 << 2), src);
        }
        asm volatile("cp.async.commit_group;");
    };
    auto load_w = [&](int ch, float4& r0, float4& r1) {
        const float* src = weight + ((size_t)(wo * KKn + ch * 8 + wk2)) * Ln + l0;
        r0 = *(const float4*)(src);
        r1 = *(const float4*)(src + 4);
    };
    auto sts_w = [&](int buf, const float4& r0, const float4& r1) {
        float* wd = w_s + buf * 4096 + wk2 * 512 + wo;   // [k2][l][o], store l=0..7
        wd[0 * 64] = r0.x; wd[1 * 64] = r0.y; wd[2 * 64] = r0.z; wd[3 * 64] = r0.w;
        wd[4 * 64] = r1.x; wd[5 * 64] = r1.y; wd[6 * 64] = r1.z; wd[7 * 64] = r1.w;
    };

    // ---- pipeline prologue ----
    issue_u(0, 0);
    float4 wr0, wr1, wn0, wn1;
    load_w(0, wr0, wr1);

    const float* wbase0 = w_s + lv * 64 + ot * 8;
    const float* ubase0 = u_s + lv * 64 + bt * 8;

    for (int ch = 0; ch < 72; ch++) {
        int buf = ch & 1;
        sts_w(buf, wr0, wr1);
        if (ch + 1 < 72) {
            issue_u(ch + 1, buf ^ 1);
            load_w(ch + 1, wn0, wn1);
            asm volatile("cp.async.wait_group 1;");
        } else {
            asm volatile("cp.async.wait_group 0;");
        }
        __syncthreads();

        const float* wb = wbase0 + buf * 4096;
        const float* ub = ubase0 + buf * 4096;
#pragma unroll
        for (int kk = 0; kk < 8; kk++) {
            ulonglong2 wa = *(const ulonglong2*)(wb + kk * 512);
            ulonglong2 wc = *(const ulonglong2*)(wb + kk * 512 + 4);
            float4 ua = *(const float4*)(ub + kk * 512);
            float4 uc = *(const float4*)(ub + kk * 512 + 4);
            unsigned long long wv[4] = { wa.x, wa.y, wc.x, wc.y };
            unsigned long long u2[8] = { pk(ua.x), pk(ua.y), pk(ua.z), pk(ua.w),
                                         pk(uc.x), pk(uc.y), pk(uc.z), pk(uc.w) };
#pragma unroll
            for (int op = 0; op < 4; op++)
#pragma unroll
                for (int j = 0; j < 8; j++)
                    FFMA2(acc[op][j], wv[op], u2[j]);
        }
        __syncthreads();
        wr0 = wn0; wr1 = wn1;
    }

    // ---- epilogue: smem transpose for 32B-per-(b,o) coalesced output writes ----
    float* s_ep = smem;   // [64 b][68 pad] : s_ep[b*68 + o_t*8 + l]
    const int wb_ = tid & 63;       // writer b
    const int wot = tid >> 6;       // writer o_t

#pragma unroll
    for (int oi = 0; oi < 8; oi++) {
        int o_mine = ot * 8 + oi;
        float bv = bias[o_mine * Ln + l0 + lv];
#pragma unroll
        for (int j = 0; j < 8; j++) {
            float2 v2 = *reinterpret_cast<float2*>(&acc[oi >> 1][j]);
            float v = (oi & 1) ? v2.y : v2.x;
            s_ep[(bt * 8 + j) * 68 + ot * 8 + lv] = v + bv;
        }
        __syncthreads();
        // each thread writes one (b, o) pair's 8 pixels (32B contiguous)
        const float* sp = s_ep + wb_ * 68 + wot * 8;
        float4 v0 = *(const float4*)(sp);
        float4 v1 = *(const float4*)(sp + 4);
        int o_w = wot * 8 + oi;
        float* dst = out + ((size_t)(wb_ * On + o_w)) * Ln + l0;
        *(float4*)(dst)     = v0;
        *(float4*)(dst + 4) = v1;
        __syncthreads();
    }
}

// ---------------------------------------------------------------------------
extern "C" void kernel_launch(void* const* d_in, const int* in_sizes, int n_in,
                              void* d_out, int out_size) {
    const float* x      = (const float*)d_in[0];
    const float* weight = (const float*)d_in[1];
    const float* bias   = (const float*)d_in[2];
    float* out = (float*)d_out;

    cudaFuncSetAttribute(lc_kernel, cudaFuncAttributeMaxDynamicSharedMemorySize, 65536);

    border_kernel<<<2112, 256>>>();
    transpose_kernel<<<Cn * Hn, 256>>>(x);
    lc_kernel<<<Ln / 8, 512, 65536>>>(weight, bias, out);
}

// round 6
// speedup vs baseline: 1.0002x; 1.0002x over previous
#include <cuda_runtime.h>
#include <cstdint>

#define Bn 64
#define Cn 64
#define On 64
#define Hn 32
#define Wn 32
#define Ln 1024
#define KKn 576
#define HP 34
#define WP 34

// padded, transposed x: [c][hp][wp][b], b innermost for coalesced unfold gathers
__device__ float g_xTp[Cn * HP * WP * Bn];

// ---------------------------------------------------------------------------
// Kernel 1: zero the padded border of g_xTp
// ---------------------------------------------------------------------------
__global__ void border_kernel() {
    int idx = blockIdx.x * 256 + threadIdx.x;       // 64 c * 132 border cells * 64 b
    if (idx >= Cn * 132 * Bn) return;
    int b = idx & 63;
    int r = idx >> 6;
    int c = r / 132;
    int cell = r % 132;
    int hp, wp;
    if (cell < 34)       { hp = 0;  wp = cell; }
    else if (cell < 68)  { hp = 33; wp = cell - 34; }
    else if (cell < 100) { hp = cell - 68 + 1;  wp = 0; }
    else                 { hp = cell - 100 + 1; wp = 33; }
    g_xTp[((c * HP + hp) * WP + wp) * Bn + b] = 0.0f;
}

// ---------------------------------------------------------------------------
// Kernel 2: transpose x (B,C,H,W) -> xTp[c][h+1][w+1][b] via smem tile
// ---------------------------------------------------------------------------
__global__ void transpose_kernel(const float* __restrict__ x) {
    __shared__ float t[32][65];
    int c = blockIdx.x & 63;
    int h = blockIdx.x >> 6;
    int tid = threadIdx.x;

    int w  = tid & 31;
    int b0 = tid >> 5;                     // 0..7
#pragma unroll
    for (int p = 0; p < 8; p++) {
        int b = b0 * 8 + p;
        t[w][b] = x[((b * Cn + c) * Hn + h) * Wn + w];  // 128B coalesced reads
    }
    __syncthreads();
    int b  = tid & 63;
    int wq = tid >> 6;                     // 0..3
#pragma unroll
    for (int p = 0; p < 8; p++) {
        int ww = wq * 8 + p;
        g_xTp[((c * HP + (h + 1)) * WP + (ww + 1)) * Bn + b] = t[ww][b];  // 256B coalesced writes
    }
}

// ---------------------------------------------------------------------------
// Kernel 3: main locally-connected GEMM
//   grid = 128 CTAs (8 pixels each), 512 threads
//   thread tid -> (b_t = tid&7, o_t = (tid>>3)&7, l = tid>>6)
//   per-thread 8o x 8b outer product at one pixel, fp32x2-packed over o
// ---------------------------------------------------------------------------
__device__ __forceinline__ void cpa16(float* dst, const float* src) {
    unsigned d = (unsigned)__cvta_generic_to_shared(dst);
    asm volatile("cp.async.cg.shared.global [%0], [%1], 16;" :: "r"(d), "l"(src));
}
__device__ __forceinline__ unsigned long long pk(float v) {
    unsigned long long r;
    asm("mov.b64 %0, {%1, %1};" : "=l"(r) : "f"(v));
    return r;
}
#define FFMA2(a, wv, uv) asm("fma.rn.f32x2 %0, %1, %2, %0;" : "+l"(a) : "l"(wv), "l"(uv))

__global__ __launch_bounds__(512, 1)
void lc_kernel(const float* __restrict__ weight, const float* __restrict__ bias,
               float* __restrict__ out) {
    extern __shared__ float smem[];
    float* w_s = smem;            // [2][8k][8l][64o]  (16KB per buf)
    float* u_s = smem + 8192;     // [2][8k][8l][64b]

    const int tid = threadIdx.x;
    const int bt  = tid & 7;
    const int ot  = (tid >> 3) & 7;
    const int lv  = tid >> 6;
    const int l0  = blockIdx.x << 3;
    const int h   = l0 >> 5;         // row (constant for the whole CTA)
    const int w0  = l0 & 31;

    // u cp.async mapping: thread covers 2 float4s (k2 and k2+4), fixed (l,b4)
    const int ub4  = tid & 15;
    const int ul   = (tid >> 4) & 7;
    const int uk2a = tid >> 7;       // 0..3

    // w LDG/STS mapping: thread covers (o, k2), 8 l-values (32B contiguous in gmem)
    const int wo  = tid & 63;
    const int wk2 = tid >> 6;        // 0..7

    unsigned long long acc[4][8];
#pragma unroll
    for (int i = 0; i < 4; i++)
#pragma unroll
        for (int j = 0; j < 8; j++) acc[i][j] = 0ULL;

    // ---- helpers as lambdas ----
    auto issue_u = [&](int ch, int buf) {
#pragma unroll
        for (int t = 0; t < 2; t++) {
            int k2 = uk2a + 4 * t;
            int k  = ch * 8 + k2;
            int c   = (k * 7282) >> 16;        // k/9, exact for k<576
            int rem = k - 9 * c;
            int i   = (rem * 11) >> 5;         // rem/3
            int j   = rem - 3 * i;
            const float* src = g_xTp + (((c * HP) + h + i) * WP + (w0 + ul + j)) * Bn + (ub4 << 2);
            cpa16(u_s + buf * 4096 + (k2 * 8 + ul) * 64 + (ub4 << 2), src);
        }
        asm volatile("cp.async.commit_group;");
    };
    auto load_w = [&](int ch, float4& r0, float4& r1) {
        const float* src = weight + ((size_t)(wo * KKn + ch * 8 + wk2)) * Ln + l0;
        r0 = *(const float4*)(src);
        r1 = *(const float4*)(src + 4);
    };
    auto sts_w = [&](int buf, const float4& r0, const float4& r1) {
        float* wd = w_s + buf * 4096 + wk2 * 512 + wo;   // [k2][l][o], store l=0..7
        wd[0 * 64] = r0.x; wd[1 * 64] = r0.y; wd[2 * 64] = r0.z; wd[3 * 64] = r0.w;
        wd[4 * 64] = r1.x; wd[5 * 64] = r1.y; wd[6 * 64] = r1.z; wd[7 * 64] = r1.w;
    };

    // ---- pipeline prologue ----
    issue_u(0, 0);
    float4 wr0, wr1, wn0, wn1;
    load_w(0, wr0, wr1);

    const float* wbase0 = w_s + lv * 64 + ot * 8;
    const float* ubase0 = u_s + lv * 64 + bt * 8;

    for (int ch = 0; ch < 72; ch++) {
        int buf = ch & 1;
        sts_w(buf, wr0, wr1);
        if (ch + 1 < 72) {
            issue_u(ch + 1, buf ^ 1);
            load_w(ch + 1, wn0, wn1);
            asm volatile("cp.async.wait_group 1;");
        } else {
            asm volatile("cp.async.wait_group 0;");
        }
        __syncthreads();

        const float* wb = wbase0 + buf * 4096;
        const float* ub = ubase0 + buf * 4096;
#pragma unroll
        for (int kk = 0; kk < 8; kk++) {
            ulonglong2 wa = *(const ulonglong2*)(wb + kk * 512);
            ulonglong2 wc = *(const ulonglong2*)(wb + kk * 512 + 4);
            float4 ua = *(const float4*)(ub + kk * 512);
            float4 uc = *(const float4*)(ub + kk * 512 + 4);
            unsigned long long wv[4] = { wa.x, wa.y, wc.x, wc.y };
            unsigned long long u2[8] = { pk(ua.x), pk(ua.y), pk(ua.z), pk(ua.w),
                                         pk(uc.x), pk(uc.y), pk(uc.z), pk(uc.w) };
#pragma unroll
            for (int op = 0; op < 4; op++)
#pragma unroll
                for (int j = 0; j < 8; j++)
                    FFMA2(acc[op][j], wv[op], u2[j]);
        }
        __syncthreads();
        wr0 = wn0; wr1 = wn1;
    }

    // ---- epilogue: smem transpose for 32B-per-(b,o) coalesced output writes ----
    float* s_ep = smem;   // [64 b][68 pad] : s_ep[b*68 + o_t*8 + l]
    const int wb_ = tid & 63;       // writer b
    const int wot = tid >> 6;       // writer o_t

#pragma unroll
    for (int oi = 0; oi < 8; oi++) {
        int o_mine = ot * 8 + oi;
        float bv = bias[o_mine * Ln + l0 + lv];
#pragma unroll
        for (int j = 0; j < 8; j++) {
            float2 v2 = *reinterpret_cast<float2*>(&acc[oi >> 1][j]);
            float v = (oi & 1) ? v2.y : v2.x;
            s_ep[(bt * 8 + j) * 68 + ot * 8 + lv] = v + bv;
        }
        __syncthreads();
        // each thread writes one (b, o) pair's 8 pixels (32B contiguous)
        const float* sp = s_ep + wb_ * 68 + wot * 8;
        float4 v0 = *(const float4*)(sp);
        float4 v1 = *(const float4*)(sp + 4);
        int o_w = wot * 8 + oi;
        float* dst = out + ((size_t)(wb_ * On + o_w)) * Ln + l0;
        *(float4*)(dst)     = v0;
        *(float4*)(dst + 4) = v1;
        __syncthreads();
    }
}

// ---------------------------------------------------------------------------
extern "C" void kernel_launch(void* const* d_in, const int* in_sizes, int n_in,
                              void* d_out, int out_size) {
    const float* x      = (const float*)d_in[0];
    const float* weight = (const float*)d_in[1];
    const float* bias   = (const float*)d_in[2];
    float* out = (float*)d_out;

    cudaFuncSetAttribute(lc_kernel, cudaFuncAttributeMaxDynamicSharedMemorySize, 65536);

    border_kernel<<<2112, 256>>>();
    transpose_kernel<<<Cn * Hn, 256>>>(x);
    lc_kernel<<<Ln / 8, 512, 65536>>>(weight, bias, out);
}

// round 8
// speedup vs baseline: 1.5631x; 1.5629x over previous
#include <cuda_runtime.h>
#include <cstdint>

#define UP 72                       // k-row pitch (words) for u/w tiles
#define TB 1152                     // per-pixel tile words: 16*72
#define UBUF 9216                   // words per buffer: 8 pix * 1152
#define OFF_W 18432                 // w tiles start (u: 2 bufs)
#define OFF_KO 36864                // koff start (w: 2 bufs end)
#define SMEM_BYTES ((OFF_KO + 576) * 4)
#define SEPP 520

__device__ float g_xTp[64 * 34 * 34 * 64];   // [c][hp][wp][b], tf32-RNA rounded

__device__ __forceinline__ uint32_t tf32r(float f) {
    uint32_t r; asm("cvt.rna.tf32.f32 %0,%1;" : "=r"(r) : "f"(f)); return r;
}
__device__ __forceinline__ uint32_t s2u(const void* p) {
    uint32_t a;
    asm("{.reg .u64 t; cvta.to.shared.u64 t,%1; cvt.u32.u64 %0,t;}" : "=r"(a) : "l"(p));
    return a;
}
__device__ __forceinline__ void cpa16(uint32_t d, const float* s) {
    asm volatile("cp.async.cg.shared.global [%0],[%1],16;" :: "r"(d), "l"(s));
}
#define MMA(d, a, b) asm volatile( \
    "mma.sync.aligned.m16n8k8.row.col.f32.tf32.tf32.f32 " \
    "{%0,%1,%2,%3},{%4,%5,%6,%7},{%8,%9},{%0,%1,%2,%3};" \
    : "+f"((d)[0]), "+f"((d)[1]), "+f"((d)[2]), "+f"((d)[3]) \
    : "r"((a)[0]), "r"((a)[1]), "r"((a)[2]), "r"((a)[3]), "r"((b)[0]), "r"((b)[1]))

// ---------------------------------------------------------------------------
__global__ void border_kernel() {
    int idx = blockIdx.x * 256 + threadIdx.x;      // 64c * 132 cells * 16 (b/4)
    if (idx >= 64 * 132 * 16) return;
    int b4 = idx & 15, r = idx >> 4;
    int c = r / 132, cell = r % 132;
    int hp, wp;
    if (cell < 34)       { hp = 0;  wp = cell; }
    else if (cell < 68)  { hp = 33; wp = cell - 34; }
    else if (cell < 100) { hp = cell - 68 + 1;  wp = 0; }
    else                 { hp = cell - 100 + 1; wp = 33; }
    *(float4*)&g_xTp[((c * 34 + hp) * 34 + wp) * 64 + b4 * 4] = make_float4(0.f, 0.f, 0.f, 0.f);
}

__global__ void transpose_kernel(const float* __restrict__ x) {
    __shared__ float t[32][65];
    int c = blockIdx.x & 63, h = blockIdx.x >> 6, tid = threadIdx.x;
    int w = tid & 31, b0 = tid >> 5;
#pragma unroll
    for (int p = 0; p < 8; p++)
        t[w][b0 * 8 + p] = x[(((b0 * 8 + p) * 64 + c) * 32 + h) * 32 + w];
    __syncthreads();
    int b = tid & 63, wq = tid >> 6;
#pragma unroll
    for (int p = 0; p < 8; p++) {
        int ww = wq * 8 + p;
        g_xTp[((c * 34 + h + 1) * 34 + ww + 1) * 64 + b] = __uint_as_float(tf32r(t[ww][b]));
    }
}

// ---------------------------------------------------------------------------
__global__ __launch_bounds__(512, 1)
void lc_kernel(const float* __restrict__ weight, const float* __restrict__ bias,
               float* __restrict__ out) {
    extern __shared__ float sm[];
    const uint32_t sb = s2u(sm);
    float* u_s = sm;
    float* w_s = sm + OFF_W;
    int* koff = (int*)(sm + OFF_KO);

    const int tid = threadIdx.x, lane = tid & 31, wrp = tid >> 5;
    const int pix = wrp >> 1, nh = wrp & 1;
    const int l0 = blockIdx.x << 3, h = l0 >> 5, w0 = l0 & 31;
    const int arow = lane >> 2, acol = lane & 3;

    for (int k = tid; k < 576; k += 512) {
        int c = k / 9, r = k - 9 * c, i = r / 3, j = r - 3 * i;
        koff[k] = (c * 1156 + i * 34 + j) * 64;
    }
    __syncthreads();

    // ---- u cp.async mapping: (b16, k, pix=up0+2i) ----
    const int ub16 = tid & 15, uk = (tid >> 4) & 15, up0 = tid >> 8;
    const float* ubase = g_xTp + (h * 34 + w0 + up0) * 64 + ub16 * 4;
    const uint32_t udst0 = sb + (uint32_t)((up0 * 16 + uk) * UP + ub16 * 4) * 4;

    // ---- w mapping: unit (o = tid&63, k = tid>>6 and +8) ----
    const int wo = tid & 63, wk0 = tid >> 6;
    const float* wsrc0 = weight + ((size_t)wo * 576 + wk0) * 1024 + l0;

    float wr[16];

    auto issue_u = [&](int ch, int buf) {
        const float* s0 = ubase + koff[ch * 16 + uk];
        uint32_t d0 = udst0 + (uint32_t)buf * (UBUF * 4);
#pragma unroll
        for (int i = 0; i < 4; i++)
            cpa16(d0 + (uint32_t)i * (2 * TB * 4), s0 + i * 2 * 64);
        asm volatile("cp.async.commit_group;" ::: "memory");
    };
    auto ldg_w = [&](int ch) {
        const float* s = wsrc0 + (size_t)ch * 16 * 1024;
        float4 a0 = *(const float4*)s, a1 = *(const float4*)(s + 4);
        const float* s2 = s + (size_t)8 * 1024;
        float4 b0 = *(const float4*)s2, b1 = *(const float4*)(s2 + 4);
        wr[0] = a0.x; wr[1] = a0.y; wr[2] = a0.z; wr[3] = a0.w;
        wr[4] = a1.x; wr[5] = a1.y; wr[6] = a1.z; wr[7] = a1.w;
        wr[8]  = b0.x; wr[9]  = b0.y; wr[10] = b0.z; wr[11] = b0.w;
        wr[12] = b1.x; wr[13] = b1.y; wr[14] = b1.z; wr[15] = b1.w;
    };
    auto sts_w = [&](int buf) {
        float* base = w_s + buf * UBUF + wk0 * UP + wo;      // [pix][k][o]
#pragma unroll
        for (int p = 0; p < 8; p++)
            base[p * TB] = __uint_as_float(tf32r(wr[p]));
        float* base2 = base + 8 * UP;
#pragma unroll
        for (int p = 0; p < 8; p++)
            base2[p * TB] = __uint_as_float(tf32r(wr[8 + p]));
    };

    float acc[16][4];
#pragma unroll
    for (int i = 0; i < 16; i++)
#pragma unroll
        for (int j = 0; j < 4; j++) acc[i][j] = 0.f;

    issue_u(0, 0);
    ldg_w(0);

    for (int ch = 0; ch < 36; ch++) {
        const int buf = ch & 1;
        sts_w(buf);
        if (ch < 35) {
            issue_u(ch + 1, buf ^ 1);
            ldg_w(ch + 1);
            asm volatile("cp.async.wait_group 1;" ::: "memory");
        } else {
            asm volatile("cp.async.wait_group 0;" ::: "memory");
        }
        __syncthreads();

        const float* A0 = u_s + buf * UBUF + pix * TB + acol * UP + arow;
        const float* B0 = w_s + buf * UBUF + pix * TB + acol * UP + nh * 32 + arow;
#pragma unroll
        for (int k8 = 0; k8 < 2; k8++) {
            uint32_t b[4][2];
#pragma unroll
            for (int nt = 0; nt < 4; nt++) {
                b[nt][0] = __float_as_uint(B0[k8 * 8 * UP + nt * 8]);
                b[nt][1] = __float_as_uint(B0[k8 * 8 * UP + 4 * UP + nt * 8]);
            }
#pragma unroll
            for (int mt = 0; mt < 4; mt++) {
                const float* Ap = A0 + k8 * 8 * UP + mt * 16;
                uint32_t a[4];
                a[0] = __float_as_uint(Ap[0]);
                a[1] = __float_as_uint(Ap[8]);
                a[2] = __float_as_uint(Ap[4 * UP]);
                a[3] = __float_as_uint(Ap[4 * UP + 8]);
#pragma unroll
                for (int nt = 0; nt < 4; nt++) MMA(acc[mt * 4 + nt], a, b[nt]);
            }
        }
        __syncthreads();    // protect buf from next iteration's refill
    }

    // ---- epilogue: stage D to smem, then coalesced 32B output lines ----
    float* sep = sm;        // [b][o][pix], pitch SEPP per b
#pragma unroll
    for (int mt = 0; mt < 4; mt++)
#pragma unroll
        for (int nt = 0; nt < 4; nt++) {
            const float* d = acc[mt * 4 + nt];
            int b_ = mt * 16 + arow;
            int o_ = nh * 32 + nt * 8 + acol * 2;
            sep[b_ * SEPP + o_ * 8 + pix]             = d[0];
            sep[b_ * SEPP + (o_ + 1) * 8 + pix]       = d[1];
            sep[(b_ + 8) * SEPP + o_ * 8 + pix]       = d[2];
            sep[(b_ + 8) * SEPP + (o_ + 1) * 8 + pix] = d[3];
        }
    __syncthreads();
#pragma unroll
    for (int it = 0; it < 8; it++) {
        int unit = tid + (it << 9);
        int o = unit & 63, b = unit >> 6;
        const float* sp = sep + b * SEPP + o * 8;
        float4 v0 = *(const float4*)sp;
        float4 v1 = *(const float4*)(sp + 4);
        float4 g0 = *(const float4*)(bias + o * 1024 + l0);
        float4 g1 = *(const float4*)(bias + o * 1024 + l0 + 4);
        float* dp = out + ((size_t)(b * 64 + o)) * 1024 + l0;
        *(float4*)dp       = make_float4(v0.x + g0.x, v0.y + g0.y, v0.z + g0.z, v0.w + g0.w);
        *(float4*)(dp + 4) = make_float4(v1.x + g1.x, v1.y + g1.y, v1.z + g1.z, v1.w + g1.w);
    }
}

// ---------------------------------------------------------------------------
extern "C" void kernel_launch(void* const* d_in, const int* in_sizes, int n_in,
                              void* d_out, int out_size) {
    const float* x      = (const float*)d_in[0];
    const float* weight = (const float*)d_in[1];
    const float* bias   = (const float*)d_in[2];
    float* out = (float*)d_out;

    cudaFuncSetAttribute(lc_kernel, cudaFuncAttributeMaxDynamicSharedMemorySize, SMEM_BYTES);

    border_kernel<<<(64 * 132 * 16 + 255) / 256, 256>>>();
    transpose_kernel<<<64 * 32, 256>>>(x);
    lc_kernel<<<128, 512, SMEM_BYTES>>>(weight, bias, out);
}